// round 1
// baseline (speedup 1.0000x reference)
#include <cuda_runtime.h>
#include <cuda_bf16.h>
#include <cstdint>

// ---------------- problem constants ----------------
#define FH_    16
#define FW_    44
#define HW_    704          // FH*FW
#define NCAM   6
#define CIN    512
#define DB     41           // depth bins
#define CT     128          // context channels
#define NO     169          // DB + CT
#define NPIX   4224         // NCAM * HW_
#define NPTS   173184       // NPIX * DB
#define NVOX   16384        // 128*128

// ---------------- scratch (__device__ globals; no allocation) ----------------
__device__ float d_invpost[NCAM * 9];
__device__ float d_combine[NCAM * 9];
__device__ float d_wT[CIN * NO];           // wT[c*NO + o] = w[o*CIN + c]
__device__ float d_feat[NPIX * NO];        // feat[pix*NO + o]
__device__ float d_dep[NPTS];              // dep[pix*DB + d]
__device__ float d_cfeat[NPIX * CT];       // cfeat[pix*CT + c]
__device__ int   d_cnt[NVOX];
__device__ int   d_offs[NVOX];
__device__ int2  d_sorted[NPTS];           // (pix, depth-as-bits)
__device__ float d_vox[NVOX * CT];         // vox[v*CT + c]

// ---------------- helpers ----------------
__device__ __forceinline__ void inv3(const float* m, float* o) {
    float a=m[0],b=m[1],c=m[2],d=m[3],e=m[4],f=m[5],g=m[6],h=m[7],i=m[8];
    float A  =  (e*i - f*h);
    float Bc = -(d*i - f*g);
    float Cc =  (d*h - e*g);
    float det = a*A + b*Bc + c*Cc;
    float inv = 1.0f / det;
    o[0] = A  * inv;           o[1] = -(b*i - c*h) * inv;  o[2] =  (b*f - c*e) * inv;
    o[3] = Bc * inv;           o[4] =  (a*i - c*g) * inv;  o[5] = -(a*f - c*d) * inv;
    o[6] = Cc * inv;           o[7] = -(a*h - b*g) * inv;  o[8] =  (a*e - b*d) * inv;
}

// ---------------- K0: per-camera matrices ----------------
__global__ void k_mats(const float* __restrict__ rots,
                       const float* __restrict__ intrins,
                       const float* __restrict__ post_rots) {
    int n = threadIdx.x;
    if (n >= NCAM) return;
    float ip[9], ii[9];
    inv3(post_rots + n * 9, ip);
    inv3(intrins  + n * 9, ii);
#pragma unroll
    for (int k = 0; k < 9; k++) d_invpost[n * 9 + k] = ip[k];
    const float* R = rots + n * 9;
#pragma unroll
    for (int i = 0; i < 3; i++)
#pragma unroll
        for (int j = 0; j < 3; j++) {
            float s = 0.f;
#pragma unroll
            for (int k = 0; k < 3; k++) s += R[i * 3 + k] * ii[k * 3 + j];
            d_combine[n * 9 + i * 3 + j] = s;
        }
}

// ---------------- weight transpose ----------------
__global__ void k_wt(const float* __restrict__ w) {
    int idx = blockIdx.x * blockDim.x + threadIdx.x;
    if (idx >= CIN * NO) return;
    int c = idx / NO, o = idx % NO;
    d_wT[idx] = w[o * CIN + c];
}

// ---------------- zero the histogram (each replay) ----------------
__global__ void k_zero() {
    int i = blockIdx.x * blockDim.x + threadIdx.x;
    if (i < NVOX) d_cnt[i] = 0;
}

// ---------------- GEMM: feat = w @ x + b ----------------
// one block = 16 pixels of one camera; thread = one output channel o
__global__ void k_gemm(const float* __restrict__ x, const float* __restrict__ bias) {
    __shared__ float xs[CIN * 16];
    int n   = blockIdx.x / 44;
    int t   = blockIdx.x % 44;
    int hw0 = t * 16;
    int tid = threadIdx.x;                 // 192 threads

    const float* xb = x + (size_t)n * CIN * HW_ + hw0;
    for (int i = tid; i < CIN * 16; i += 192) {
        int c = i >> 4, j = i & 15;
        xs[i] = xb[c * HW_ + j];
    }
    __syncthreads();

    if (tid < NO) {
        float acc[16];
#pragma unroll
        for (int j = 0; j < 16; j++) acc[j] = 0.f;
        const float* wp = d_wT + tid;
#pragma unroll 4
        for (int c = 0; c < CIN; c++) {
            float wv = wp[c * NO];
            float4 a0 = *(const float4*)&xs[c * 16 + 0];
            float4 a1 = *(const float4*)&xs[c * 16 + 4];
            float4 a2 = *(const float4*)&xs[c * 16 + 8];
            float4 a3 = *(const float4*)&xs[c * 16 + 12];
            acc[0]  = fmaf(wv, a0.x, acc[0]);  acc[1]  = fmaf(wv, a0.y, acc[1]);
            acc[2]  = fmaf(wv, a0.z, acc[2]);  acc[3]  = fmaf(wv, a0.w, acc[3]);
            acc[4]  = fmaf(wv, a1.x, acc[4]);  acc[5]  = fmaf(wv, a1.y, acc[5]);
            acc[6]  = fmaf(wv, a1.z, acc[6]);  acc[7]  = fmaf(wv, a1.w, acc[7]);
            acc[8]  = fmaf(wv, a2.x, acc[8]);  acc[9]  = fmaf(wv, a2.y, acc[9]);
            acc[10] = fmaf(wv, a2.z, acc[10]); acc[11] = fmaf(wv, a2.w, acc[11]);
            acc[12] = fmaf(wv, a3.x, acc[12]); acc[13] = fmaf(wv, a3.y, acc[13]);
            acc[14] = fmaf(wv, a3.z, acc[14]); acc[15] = fmaf(wv, a3.w, acc[15]);
        }
        float b = bias[tid];
        int pix0 = n * HW_ + hw0;
#pragma unroll
        for (int j = 0; j < 16; j++)
            d_feat[(pix0 + j) * NO + tid] = acc[j] + b;
    }
}

// ---------------- softmax over depth bins + cfeat copy ----------------
__global__ void k_softmax() {
    int pix = blockIdx.x;
    const float* f = d_feat + pix * NO;
    int tid = threadIdx.x;                 // 128
    d_cfeat[pix * CT + tid] = f[DB + tid];
    if (tid < 32) {
        const float NEG = -3.4e38f;
        float v0 = (tid      < DB) ? f[tid]      : NEG;
        float v1 = (tid + 32 < DB) ? f[tid + 32] : NEG;
        float m = fmaxf(v0, v1);
#pragma unroll
        for (int o = 16; o; o >>= 1) m = fmaxf(m, __shfl_xor_sync(0xffffffffu, m, o));
        float e0 = (tid      < DB) ? expf(v0 - m) : 0.f;
        float e1 = (tid + 32 < DB) ? expf(v1 - m) : 0.f;
        float s = e0 + e1;
#pragma unroll
        for (int o = 16; o; o >>= 1) s += __shfl_xor_sync(0xffffffffu, s, o);
        float inv = 1.0f / s;
        if (tid      < DB) d_dep[pix * DB + tid]      = e0 * inv;
        if (tid + 32 < DB) d_dep[pix * DB + tid + 32] = e1 * inv;
    }
}

// ---------------- geometry -> voxel rank + histogram ----------------
__device__ int d_rank[NPTS];

__global__ void k_rank(const float* __restrict__ trans,
                       const float* __restrict__ post_trans) {
    int p = blockIdx.x * blockDim.x + threadIdx.x;
    if (p >= NPTS) return;
    int d   = p % DB;
    int pix = p / DB;
    int n   = pix / HW_;
    int hw  = pix % HW_;
    int h   = hw / FW_;
    int w   = hw % FW_;

    float xsv = (float)w * (703.0f / 43.0f);
    float ysv = (float)h * 17.0f;
    float dsv = 4.0f + (float)d;

    float px = xsv - post_trans[n * 3 + 0];
    float py = ysv - post_trans[n * 3 + 1];
    float pz = dsv - post_trans[n * 3 + 2];
    const float* IP = d_invpost + n * 9;
    float qx = IP[0]*px + IP[1]*py + IP[2]*pz;
    float qy = IP[3]*px + IP[4]*py + IP[5]*pz;
    float qz = IP[6]*px + IP[7]*py + IP[8]*pz;
    float rx = qx * qz, ry = qy * qz, rz = qz;
    const float* C = d_combine + n * 9;
    float gx = C[0]*rx + C[1]*ry + C[2]*rz + trans[n * 3 + 0];
    float gy = C[3]*rx + C[4]*ry + C[5]*rz + trans[n * 3 + 1];
    float gz = C[6]*rx + C[7]*ry + C[8]*rz + trans[n * 3 + 2];

    // truncation toward zero, matching jnp astype(int32)
    int ix = (int)((gx + 51.2f) / 0.8f);
    int iy = (int)((gy + 51.2f) / 0.8f);
    int iz = (int)((gz + 10.0f) / 20.0f);
    bool valid = (ix >= 0) & (ix < 128) & (iy >= 0) & (iy < 128) & (iz == 0);
    int r = valid ? (iy * 128 + ix) : NVOX;
    d_rank[p] = r;
    if (r < NVOX) atomicAdd(&d_cnt[r], 1);
}

// ---------------- exclusive scan of 16384 counts (1 block, 1024 thr) ----------------
__global__ void k_scan() {
    __shared__ int wsum[32];
    int t = threadIdx.x, lane = t & 31, wid = t >> 5;
    int base = t * 16;
    int s = 0;
#pragma unroll
    for (int k = 0; k < 16; k++) s += d_cnt[base + k];
    int val = s;
#pragma unroll
    for (int o = 1; o < 32; o <<= 1) {
        int u = __shfl_up_sync(0xffffffffu, val, o);
        if (lane >= o) val += u;
    }
    if (lane == 31) wsum[wid] = val;
    __syncthreads();
    if (wid == 0) {
        int wv = wsum[lane];
#pragma unroll
        for (int o = 1; o < 32; o <<= 1) {
            int u = __shfl_up_sync(0xffffffffu, wv, o);
            if (lane >= o) wv += u;
        }
        wsum[lane] = wv;
    }
    __syncthreads();
    int warpbase = (wid == 0) ? 0 : wsum[wid - 1];
    int run = warpbase + val - s;      // exclusive prefix for this thread's chunk
#pragma unroll
    for (int k = 0; k < 16; k++) {
        d_offs[base + k] = run;
        run += d_cnt[base + k];
    }
}

// ---------------- scatter points into bins ----------------
__global__ void k_scatter() {
    int p = blockIdx.x * blockDim.x + threadIdx.x;
    if (p >= NPTS) return;
    int r = d_rank[p];
    if (r < NVOX) {
        int pos = atomicAdd(&d_offs[r], 1);
        int pix = p / DB;
        d_sorted[pos] = make_int2(pix, __float_as_int(d_dep[p]));
    }
}

// ---------------- gather: per-voxel accumulate ----------------
// after scatter: d_offs[v] == end of bin v; start = d_offs[v-1] (or 0)
__global__ void k_gather() {
    int v = blockIdx.x;
    int start = (v == 0) ? 0 : d_offs[v - 1];
    int end   = d_offs[v];
    int c = threadIdx.x;                   // 128
    float acc = 0.f;
    for (int i = start; i < end; i++) {
        int2 pd = d_sorted[i];
        acc = fmaf(__int_as_float(pd.y), d_cfeat[pd.x * CT + c], acc);
    }
    d_vox[v * CT + c] = acc;
}

// ---------------- final transpose vox[v][c] -> out[c][v] ----------------
__global__ void k_tr(float* __restrict__ out) {
    __shared__ float tile[32][33];
    int v0 = blockIdx.x * 32;
    int c0 = blockIdx.y * 32;
    int tx = threadIdx.x, ty = threadIdx.y;   // 32 x 8
#pragma unroll
    for (int k = 0; k < 32; k += 8)
        tile[ty + k][tx] = d_vox[(v0 + ty + k) * CT + c0 + tx];
    __syncthreads();
#pragma unroll
    for (int k = 0; k < 32; k += 8)
        out[(c0 + ty + k) * NVOX + v0 + tx] = tile[tx][ty + k];
}

// ---------------- launch ----------------
extern "C" void kernel_launch(void* const* d_in, const int* in_sizes, int n_in,
                              void* d_out, int out_size) {
    const float* x          = (const float*)d_in[0];
    const float* rots       = (const float*)d_in[1];
    const float* trans      = (const float*)d_in[2];
    const float* intrins    = (const float*)d_in[3];
    const float* post_rots  = (const float*)d_in[4];
    const float* post_trans = (const float*)d_in[5];
    const float* w_depth    = (const float*)d_in[6];
    const float* b_depth    = (const float*)d_in[7];
    float* out = (float*)d_out;

    k_mats<<<1, 32>>>(rots, intrins, post_rots);
    k_wt<<<(CIN * NO + 255) / 256, 256>>>(w_depth);
    k_zero<<<(NVOX + 255) / 256, 256>>>();
    k_gemm<<<NCAM * 44, 192>>>(x, b_depth);
    k_softmax<<<NPIX, 128>>>();
    k_rank<<<(NPTS + 255) / 256, 256>>>(trans, post_trans);
    k_scan<<<1, 1024>>>();
    k_scatter<<<(NPTS + 255) / 256, 256>>>();
    k_gather<<<NVOX, 128>>>();
    k_tr<<<dim3(NVOX / 32, CT / 32), dim3(32, 8)>>>(out);
}